// round 12
// baseline (speedup 1.0000x reference)
#include <cuda_runtime.h>
#include <cuda_fp16.h>
#include <cstdint>

#define NN 100000
#define EE 3200000
#define DD 256
#define HH 256
#define GG 512
#define CAP 96                      // per-node bucket capacity (~11 sigma above mean degree 32)

// ---------------- device scratch ----------------
__device__ int          g_deg[NN];                   // true degree (from k_count)
__device__ int          g_cursor[NN];                // bucket cursor for fill
__device__ int          g_col[(size_t)NN * CAP];     // padded adjacency buckets (38.4MB)
__device__ __half       g_xh[(size_t)NN * DD];       // norm-prescaled x, fp16 (51MB)
__device__ __half       g_ah[(size_t)NN * DD];       // aggregated features, fp16 (51MB)
__device__ __half       g_w1h[HH * DD];              // W1 in fp16
__device__ unsigned int g_pooled[GG * HH];
__device__ int          g_flags[2];                  // [0]=edge_index is int64, [1]=batch is int64

// ---------------- helpers ----------------
__device__ __forceinline__ int load_i(const void* p, int is64, long long idx) {
    if (is64) return (int)((const long long*)p)[idx];
    return ((const int*)p)[idx];
}

__device__ __forceinline__ uint32_t smem_u32(const void* p) {
    uint32_t a;
    asm("{ .reg .u64 t; cvta.to.shared.u64 t, %1; cvt.u32.u64 %0, t; }" : "=r"(a) : "l"(p));
    return a;
}

#define CP_ASYNC16(sa, ga, sz) \
    asm volatile("cp.async.ca.shared.global [%0], [%1], 16, %2;" :: "r"(sa), "l"(ga), "r"(sz))
#define CP_COMMIT() asm volatile("cp.async.commit_group;" ::: "memory")
#define CP_WAIT(n)  asm volatile("cp.async.wait_group %0;" :: "n"(n) : "memory")

__device__ __forceinline__ void add8(float* a, uint4 v) {
    float2 f;
    f = __half22float2(*(__half2*)&v.x); a[0] += f.x; a[1] += f.y;
    f = __half22float2(*(__half2*)&v.y); a[2] += f.x; a[3] += f.y;
    f = __half22float2(*(__half2*)&v.z); a[4] += f.x; a[5] += f.y;
    f = __half22float2(*(__half2*)&v.w); a[6] += f.x; a[7] += f.y;
}

// packed fp16 add of two gathered rows (one rounding per element)
__device__ __forceinline__ uint4 hadd2x4(uint4 a, uint4 b) {
    uint4 r;
    *(__half2*)&r.x = __hadd2(*(__half2*)&a.x, *(__half2*)&b.x);
    *(__half2*)&r.y = __hadd2(*(__half2*)&a.y, *(__half2*)&b.y);
    *(__half2*)&r.z = __hadd2(*(__half2*)&a.z, *(__half2*)&b.z);
    *(__half2*)&r.w = __hadd2(*(__half2*)&a.w, *(__half2*)&b.w);
    return r;
}

// zero deg/cursor/pooled, convert W1 -> fp16, dtype sniff (block 0)
__global__ void k_prep(const float* __restrict__ W1, const int* ei_w, const int* batch_w) {
    if (blockIdx.x == 0 && threadIdx.x == 0) {
        int z = 0;
        for (int k = 0; k < 64; k++) z |= ei_w[2 * k + 1];
        g_flags[0] = (z == 0);
        int z2 = 0;
        const int base = NN / 2;
        for (int k = 0; k < 32; k++) z2 |= batch_w[base + 2 * k + 1];
        g_flags[1] = (z2 == 0);
    }
    int i = blockIdx.x * blockDim.x + threadIdx.x;
    int stride = gridDim.x * blockDim.x;
    for (int j = i; j < NN; j += stride) { g_deg[j] = 0; g_cursor[j] = 0; }
    for (int j = i; j < GG * HH; j += stride) g_pooled[j] = 0u;   // 0.0f bits; relu>=0
    for (int j = i; j < HH * DD; j += stride) g_w1h[j] = __float2half(W1[j]);
}

// degree count over src column only (enables fill/half stream overlap)
__global__ void k_count(const void* ei) {
    int e = (blockIdx.x * blockDim.x + threadIdx.x) * 2;
    if (e >= EE) return;
    int is64 = g_flags[0];
    atomicAdd(&g_deg[load_i(ei, is64, e)], 1);
    if (e + 1 < EE) atomicAdd(&g_deg[load_i(ei, is64, e + 1)], 1);
}

// bucket scatter: col[src*CAP + cnt] = dst; 2 edges per thread
__global__ void k_fill(const void* ei) {
    int e = (blockIdx.x * blockDim.x + threadIdx.x) * 2;
    if (e >= EE) return;
    int is64 = g_flags[0];
    int s0 = load_i(ei, is64, e);
    int d0 = load_i(ei, is64, (long long)EE + e);
    int c0 = atomicAdd(&g_cursor[s0], 1);
    if (c0 < CAP) g_col[(size_t)s0 * CAP + c0] = d0;
    if (e + 1 < EE) {
        int s1 = load_i(ei, is64, e + 1);
        int d1 = load_i(ei, is64, (long long)EE + e + 1);
        int c1 = atomicAdd(&g_cursor[s1], 1);
        if (c1 < CAP) g_col[(size_t)s1 * CAP + c1] = d1;
    }
}

// xs = rsqrt(deg[row]) * x, stored fp16   (deg from k_count; independent of k_fill)
__global__ void k_half(const float* __restrict__ x) {
    int i = blockIdx.x * blockDim.x + threadIdx.x;   // over N*64 float4
    if (i >= NN * 64) return;
    float nr = rsqrtf((float)g_deg[i >> 6]);         // broadcast load per row
    float4 v = ((const float4*)x)[i];
    __half2* o = (__half2*)g_xh;
    o[i * 2 + 0] = __floats2half2_rn(nr * v.x, nr * v.y);
    o[i * 2 + 1] = __floats2half2_rn(nr * v.z, nr * v.w);
}

// agg[i] = norm[i] * (sum_{j in bucket(i)} xs[j] + xs[i]); warp per node,
// 8-edge unroll, pairwise fp16 HADD2 then fp32 accumulate (R10-proven)
__global__ void k_agg() {
    int node = (blockIdx.x << 3) + (threadIdx.x >> 5);
    if (node >= NN) return;
    int t = threadIdx.x & 31;
    int deg = g_deg[node];
    int cnt = min(deg, CAP);
    const int* col = &g_col[(size_t)node * CAP];
    const uint4* xr = (const uint4*)g_xh;    // 8 halves per lane

    float acc[8];
    {   // self term
        uint4 v = xr[(size_t)node * 32 + t];
        float2 f;
        f = __half22float2(*(__half2*)&v.x); acc[0] = f.x; acc[1] = f.y;
        f = __half22float2(*(__half2*)&v.y); acc[2] = f.x; acc[3] = f.y;
        f = __half22float2(*(__half2*)&v.z); acc[4] = f.x; acc[5] = f.y;
        f = __half22float2(*(__half2*)&v.w); acc[6] = f.x; acc[7] = f.y;
    }
    int p = 0;
    for (; p + 7 < cnt; p += 8) {
        int j0 = col[p],     j1 = col[p + 1], j2 = col[p + 2], j3 = col[p + 3];
        int j4 = col[p + 4], j5 = col[p + 5], j6 = col[p + 6], j7 = col[p + 7];
        uint4 v0 = __ldg(&xr[(size_t)j0 * 32 + t]);
        uint4 v1 = __ldg(&xr[(size_t)j1 * 32 + t]);
        uint4 v2 = __ldg(&xr[(size_t)j2 * 32 + t]);
        uint4 v3 = __ldg(&xr[(size_t)j3 * 32 + t]);
        uint4 v4 = __ldg(&xr[(size_t)j4 * 32 + t]);
        uint4 v5 = __ldg(&xr[(size_t)j5 * 32 + t]);
        uint4 v6 = __ldg(&xr[(size_t)j6 * 32 + t]);
        uint4 v7 = __ldg(&xr[(size_t)j7 * 32 + t]);
        add8(acc, hadd2x4(v0, v1));
        add8(acc, hadd2x4(v2, v3));
        add8(acc, hadd2x4(v4, v5));
        add8(acc, hadd2x4(v6, v7));
    }
    for (; p + 1 < cnt; p += 2) {
        uint4 v0 = __ldg(&xr[(size_t)col[p] * 32 + t]);
        uint4 v1 = __ldg(&xr[(size_t)col[p + 1] * 32 + t]);
        add8(acc, hadd2x4(v0, v1));
    }
    if (p < cnt) add8(acc, __ldg(&xr[(size_t)col[p] * 32 + t]));

    float ni = rsqrtf((float)deg);
    uint4 o;
    *(__half2*)&o.x = __floats2half2_rn(ni * acc[0], ni * acc[1]);
    *(__half2*)&o.y = __floats2half2_rn(ni * acc[2], ni * acc[3]);
    *(__half2*)&o.z = __floats2half2_rn(ni * acc[4], ni * acc[5]);
    *(__half2*)&o.w = __floats2half2_rn(ni * acc[6], ni * acc[7]);
    ((uint4*)g_ah)[(size_t)node * 32 + t] = o;
}

// ---------------- fp16 mma GEMM: h = relu(agg @ W1^T + b1), fused pool ----------------
// Block 128x128, BK=32 halves, double-buffered cp.async; 8 warps 2(M)x4(N), warp 64x32.
#define ASTR 40                                     // halves per smem row (80B, conflict-free)
#define SM_A 0                                      // [2][128*ASTR] halves
#define SM_B (2 * 128 * ASTR)                       // [2][128*ASTR]
#define SM_C (4 * 128 * ASTR)                       // Ct [128][132] halves
#define CT_STRIDE 132
#define SM_SB (SM_C + 128 * CT_STRIDE)              // sb [128] ints (half-indexed)
#define GEMM_SMEM ((SM_SB + 256) * 2)               // bytes

__device__ __forceinline__ void mma16816(float* c, const uint32_t* a, const uint32_t* b) {
    asm volatile(
        "mma.sync.aligned.m16n8k16.row.col.f32.f16.f16.f32 "
        "{%0,%1,%2,%3}, {%4,%5,%6,%7}, {%8,%9}, {%0,%1,%2,%3};"
        : "+f"(c[0]), "+f"(c[1]), "+f"(c[2]), "+f"(c[3])
        : "r"(a[0]), "r"(a[1]), "r"(a[2]), "r"(a[3]), "r"(b[0]), "r"(b[1]));
}

__global__ void __launch_bounds__(256, 2) k_gemm(const float* __restrict__ b1,
                                                 const void* batch) {
    extern __shared__ __half sh[];
    __half* Ct = sh + SM_C;
    int* sb = (int*)(sh + SM_SB);
    uint32_t sbase = smem_u32(sh);

    int tid = threadIdx.x;
    int wid = tid >> 5, lane = tid & 31;
    int m0 = blockIdx.y * 128, n0 = blockIdx.x * 128;
    int wm = (wid & 1) * 64, wn = (wid >> 1) * 32;
    int g4 = lane >> 2, t4 = lane & 3;

    float c[4][4][4];
#pragma unroll
    for (int a = 0; a < 4; a++)
#pragma unroll
        for (int b = 0; b < 4; b++)
#pragma unroll
            for (int k = 0; k < 4; k++) c[a][b][k] = 0.f;

    int lr = tid >> 2, lq = (tid & 3) * 8;

    auto issue = [&](int buf, int k0) {
#pragma unroll
        for (int it = 0; it < 2; it++) {
            int r = lr + it * 64;
            int m = m0 + r;
            const __half* ga = &g_ah[(size_t)(m < NN ? m : 0) * DD + k0 + lq];
            uint32_t sa = sbase + (SM_A + buf * 128 * ASTR + r * ASTR + lq) * 2;
            CP_ASYNC16(sa, ga, (m < NN) ? 16 : 0);
            const __half* gb = &g_w1h[(n0 + r) * DD + k0 + lq];
            uint32_t sbb = sbase + (SM_B + buf * 128 * ASTR + r * ASTR + lq) * 2;
            CP_ASYNC16(sbb, gb, 16);
        }
        CP_COMMIT();
    };

    issue(0, 0);
    for (int i = 0; i < 8; i++) {
        if (i < 7) { issue((i + 1) & 1, (i + 1) * 32); CP_WAIT(1); }
        else       { CP_WAIT(0); }
        __syncthreads();

        const __half* A = sh + SM_A + (i & 1) * 128 * ASTR;
        const __half* B = sh + SM_B + (i & 1) * 128 * ASTR;
#pragma unroll
        for (int ks = 0; ks < 2; ks++) {
            int kk = ks * 16;
            uint32_t af[4][4], bf[4][2];
#pragma unroll
            for (int mf = 0; mf < 4; mf++) {
                int row = wm + mf * 16;
                af[mf][0] = *(const uint32_t*)&A[(row + g4) * ASTR + kk + 2 * t4];
                af[mf][1] = *(const uint32_t*)&A[(row + 8 + g4) * ASTR + kk + 2 * t4];
                af[mf][2] = *(const uint32_t*)&A[(row + g4) * ASTR + kk + 8 + 2 * t4];
                af[mf][3] = *(const uint32_t*)&A[(row + 8 + g4) * ASTR + kk + 8 + 2 * t4];
            }
#pragma unroll
            for (int nf = 0; nf < 4; nf++) {
                int nr = wn + nf * 8 + g4;
                bf[nf][0] = *(const uint32_t*)&B[nr * ASTR + kk + 2 * t4];
                bf[nf][1] = *(const uint32_t*)&B[nr * ASTR + kk + 8 + 2 * t4];
            }
#pragma unroll
            for (int mf = 0; mf < 4; mf++)
#pragma unroll
                for (int nf = 0; nf < 4; nf++) mma16816(c[mf][nf], af[mf], bf[nf]);
        }
        __syncthreads();
    }

    // epilogue: bias + relu -> Ct (half)
#pragma unroll
    for (int mf = 0; mf < 4; mf++) {
        int mr = wm + mf * 16 + g4;
#pragma unroll
        for (int nf = 0; nf < 4; nf++) {
            int nc = wn + nf * 8 + t4 * 2;
            float bi0 = b1[n0 + nc], bi1 = b1[n0 + nc + 1];
            *(__half2*)&Ct[mr * CT_STRIDE + nc] =
                __floats2half2_rn(fmaxf(c[mf][nf][0] + bi0, 0.f), fmaxf(c[mf][nf][1] + bi1, 0.f));
            *(__half2*)&Ct[(mr + 8) * CT_STRIDE + nc] =
                __floats2half2_rn(fmaxf(c[mf][nf][2] + bi0, 0.f), fmaxf(c[mf][nf][3] + bi1, 0.f));
        }
    }
    if (tid < 128) {
        int m = m0 + tid;
        sb[tid] = (m < NN) ? load_i(batch, g_flags[1], m) : -1;
    }
    __syncthreads();

    // pooling: batch sorted -> run-length max per column, few atomics per block
    int col = tid & 127;
    int r0 = (tid >> 7) * 64;
    int cur = sb[r0];
    float mx = __half2float(Ct[r0 * CT_STRIDE + col]);
    for (int r = r0 + 1; r < r0 + 64; r++) {
        int gg = sb[r];
        float v = __half2float(Ct[r * CT_STRIDE + col]);
        if (gg != cur) {
            if (cur >= 0) atomicMax(&g_pooled[cur * HH + n0 + col], __float_as_uint(mx));
            cur = gg; mx = v;
        } else {
            mx = fmaxf(mx, v);
        }
    }
    if (cur >= 0) atomicMax(&g_pooled[cur * HH + n0 + col], __float_as_uint(mx));
}

// out[g] = pooled[g,:] . W2 + b2
__global__ void k_out(const float* __restrict__ W2, const float* __restrict__ b2,
                      float* __restrict__ out) {
    int warp = (blockIdx.x * blockDim.x + threadIdx.x) >> 5;
    int lane = threadIdx.x & 31;
    if (warp >= GG) return;
    float s = 0.f;
    for (int c = lane; c < HH; c += 32)
        s += __uint_as_float(g_pooled[warp * HH + c]) * W2[c];
#pragma unroll
    for (int off = 16; off; off >>= 1) s += __shfl_down_sync(0xffffffffu, s, off);
    if (lane == 0) out[warp] = s + b2[0];
}

// ---------------- launch ----------------
extern "C" void kernel_launch(void* const* d_in, const int* in_sizes, int n_in,
                              void* d_out, int out_size) {
    const float* x   = (const float*)d_in[0];
    const void*  ei  = d_in[1];
    const void*  bat = d_in[2];
    const float* W1  = (const float*)d_in[3];
    const float* b1  = (const float*)d_in[4];
    const float* W2  = (const float*)d_in[5];
    const float* b2  = (const float*)d_in[6];
    float* out = (float*)d_out;

    static bool init_done = false;
    static cudaStream_t s1;
    static cudaEvent_t ev_fork, ev_join;
    if (!init_done) {
        cudaFuncSetAttribute(k_gemm, cudaFuncAttributeMaxDynamicSharedMemorySize, GEMM_SMEM);
        cudaStreamCreateWithFlags(&s1, cudaStreamNonBlocking);
        cudaEventCreateWithFlags(&ev_fork, cudaEventDisableTiming);
        cudaEventCreateWithFlags(&ev_join, cudaEventDisableTiming);
        init_done = true;
    }

    k_prep<<<256, 256>>>(W1, (const int*)ei, (const int*)bat);
    k_count<<<(EE / 2 + 255) / 256, 256>>>(ei);
    // fork: fill (atomic-bound) on main stream, half (DRAM-bound) on s1
    cudaEventRecord(ev_fork, 0);
    cudaStreamWaitEvent(s1, ev_fork, 0);
    k_fill<<<(EE / 2 + 255) / 256, 256>>>(ei);
    k_half<<<(NN * 64 + 255) / 256, 256, 0, s1>>>(x);
    cudaEventRecord(ev_join, s1);
    cudaStreamWaitEvent(0, ev_join, 0);
    // join: agg needs both
    k_agg<<<(NN + 7) / 8, 256>>>();
    dim3 gg(HH / 128, (NN + 127) / 128);
    k_gemm<<<gg, 256, GEMM_SMEM>>>(b1, bat);
    k_out<<<(GG * 32 + 127) / 128, 128>>>(W2, b2, out);
}

// round 14
// speedup vs baseline: 1.0986x; 1.0986x over previous
#include <cuda_runtime.h>
#include <cuda_fp16.h>
#include <cstdint>

#define NN 100000
#define EE 3200000
#define DD 256
#define HH 256
#define GG 512
#define CAP 96                      // per-node bucket capacity (~11 sigma above mean degree 32)

// ---------------- device scratch ----------------
__device__ int          g_cursor[NN];                // degree counter / bucket cursor
__device__ int          g_col[(size_t)NN * CAP];     // padded adjacency buckets (38.4MB)
__device__ __half       g_xh[(size_t)NN * DD];       // norm-prescaled x, fp16 (51MB)
__device__ __half       g_ah[(size_t)NN * DD];       // aggregated features, fp16 (51MB)
__device__ __half       g_w1h[HH * DD];              // W1 in fp16
__device__ unsigned int g_pooled[GG * HH];
__device__ int          g_flags[2];                  // [0]=edge_index is int64, [1]=batch is int64

// ---------------- helpers ----------------
__device__ __forceinline__ int load_i(const void* p, int is64, long long idx) {
    if (is64) return (int)((const long long*)p)[idx];
    return ((const int*)p)[idx];
}

__device__ __forceinline__ uint32_t smem_u32(const void* p) {
    uint32_t a;
    asm("{ .reg .u64 t; cvta.to.shared.u64 t, %1; cvt.u32.u64 %0, t; }" : "=r"(a) : "l"(p));
    return a;
}

#define CP_ASYNC16(sa, ga, sz) \
    asm volatile("cp.async.ca.shared.global [%0], [%1], 16, %2;" :: "r"(sa), "l"(ga), "r"(sz))
#define CP_COMMIT() asm volatile("cp.async.commit_group;" ::: "memory")
#define CP_WAIT(n)  asm volatile("cp.async.wait_group %0;" :: "n"(n) : "memory")

__device__ __forceinline__ void add8(float* a, uint4 v) {
    float2 f;
    f = __half22float2(*(__half2*)&v.x); a[0] += f.x; a[1] += f.y;
    f = __half22float2(*(__half2*)&v.y); a[2] += f.x; a[3] += f.y;
    f = __half22float2(*(__half2*)&v.z); a[4] += f.x; a[5] += f.y;
    f = __half22float2(*(__half2*)&v.w); a[6] += f.x; a[7] += f.y;
}

// packed fp16 add of two gathered rows (one rounding per element)
__device__ __forceinline__ uint4 hadd2x4(uint4 a, uint4 b) {
    uint4 r;
    *(__half2*)&r.x = __hadd2(*(__half2*)&a.x, *(__half2*)&b.x);
    *(__half2*)&r.y = __hadd2(*(__half2*)&a.y, *(__half2*)&b.y);
    *(__half2*)&r.z = __hadd2(*(__half2*)&a.z, *(__half2*)&b.z);
    *(__half2*)&r.w = __hadd2(*(__half2*)&a.w, *(__half2*)&b.w);
    return r;
}

// zero cursor+pooled, convert W1 -> fp16, dtype sniff (block 0)
__global__ void k_prep(const float* __restrict__ W1, const int* ei_w, const int* batch_w) {
    if (blockIdx.x == 0 && threadIdx.x == 0) {
        int z = 0;
        for (int k = 0; k < 64; k++) z |= ei_w[2 * k + 1];
        g_flags[0] = (z == 0);
        int z2 = 0;
        const int base = NN / 2;
        for (int k = 0; k < 32; k++) z2 |= batch_w[base + 2 * k + 1];
        g_flags[1] = (z2 == 0);
    }
    int i = blockIdx.x * blockDim.x + threadIdx.x;
    int stride = gridDim.x * blockDim.x;
    for (int j = i; j < NN; j += stride) g_cursor[j] = 0;
    for (int j = i; j < GG * HH; j += stride) g_pooled[j] = 0u;   // 0.0f bits; relu>=0
    for (int j = i; j < HH * DD; j += stride) g_w1h[j] = __float2half(W1[j]);
}

// bucket scatter: col[src*CAP + cnt] = dst; 2 edges per thread
__global__ void k_fill(const void* ei) {
    int e = (blockIdx.x * blockDim.x + threadIdx.x) * 2;
    if (e >= EE) return;
    int is64 = g_flags[0];
    int s0 = load_i(ei, is64, e);
    int d0 = load_i(ei, is64, (long long)EE + e);
    int c0 = atomicAdd(&g_cursor[s0], 1);
    if (c0 < CAP) g_col[(size_t)s0 * CAP + c0] = d0;
    if (e + 1 < EE) {
        int s1 = load_i(ei, is64, e + 1);
        int d1 = load_i(ei, is64, (long long)EE + e + 1);
        int c1 = atomicAdd(&g_cursor[s1], 1);
        if (c1 < CAP) g_col[(size_t)s1 * CAP + c1] = d1;
    }
}

// xs = rsqrt(deg[row]) * x, stored fp16  (after k_fill: cursor==degree)
// 2 float4 per thread for load-level parallelism
__global__ void k_half(const float* __restrict__ x) {
    int i = (blockIdx.x * blockDim.x + threadIdx.x) * 2;   // over N*64 float4
    if (i >= NN * 64) return;
    const float4* xi = (const float4*)x;
    __half2* o = (__half2*)g_xh;
    float4 v0 = xi[i];
    float4 v1 = xi[i + 1];                                  // same row (64 f4/row, i even)
    float nr = rsqrtf((float)g_cursor[i >> 6]);
    o[i * 2 + 0] = __floats2half2_rn(nr * v0.x, nr * v0.y);
    o[i * 2 + 1] = __floats2half2_rn(nr * v0.z, nr * v0.w);
    o[i * 2 + 2] = __floats2half2_rn(nr * v1.x, nr * v1.y);
    o[i * 2 + 3] = __floats2half2_rn(nr * v1.z, nr * v1.w);
}

// agg[i] = norm[i] * (sum_{j in bucket(i)} xs[j] + xs[i]); warp per node,
// 8-edge unroll, pairwise fp16 HADD2 then fp32 accumulate (R10-proven best)
__global__ void k_agg() {
    int node = (blockIdx.x << 3) + (threadIdx.x >> 5);
    if (node >= NN) return;
    int t = threadIdx.x & 31;
    int deg = g_cursor[node];
    int cnt = min(deg, CAP);
    const int* col = &g_col[(size_t)node * CAP];
    const uint4* xr = (const uint4*)g_xh;    // 8 halves per lane

    float acc[8];
    {   // self term
        uint4 v = xr[(size_t)node * 32 + t];
        float2 f;
        f = __half22float2(*(__half2*)&v.x); acc[0] = f.x; acc[1] = f.y;
        f = __half22float2(*(__half2*)&v.y); acc[2] = f.x; acc[3] = f.y;
        f = __half22float2(*(__half2*)&v.z); acc[4] = f.x; acc[5] = f.y;
        f = __half22float2(*(__half2*)&v.w); acc[6] = f.x; acc[7] = f.y;
    }
    int p = 0;
    for (; p + 7 < cnt; p += 8) {
        int j0 = col[p],     j1 = col[p + 1], j2 = col[p + 2], j3 = col[p + 3];
        int j4 = col[p + 4], j5 = col[p + 5], j6 = col[p + 6], j7 = col[p + 7];
        uint4 v0 = __ldg(&xr[(size_t)j0 * 32 + t]);
        uint4 v1 = __ldg(&xr[(size_t)j1 * 32 + t]);
        uint4 v2 = __ldg(&xr[(size_t)j2 * 32 + t]);
        uint4 v3 = __ldg(&xr[(size_t)j3 * 32 + t]);
        uint4 v4 = __ldg(&xr[(size_t)j4 * 32 + t]);
        uint4 v5 = __ldg(&xr[(size_t)j5 * 32 + t]);
        uint4 v6 = __ldg(&xr[(size_t)j6 * 32 + t]);
        uint4 v7 = __ldg(&xr[(size_t)j7 * 32 + t]);
        add8(acc, hadd2x4(v0, v1));
        add8(acc, hadd2x4(v2, v3));
        add8(acc, hadd2x4(v4, v5));
        add8(acc, hadd2x4(v6, v7));
    }
    for (; p + 1 < cnt; p += 2) {
        uint4 v0 = __ldg(&xr[(size_t)col[p] * 32 + t]);
        uint4 v1 = __ldg(&xr[(size_t)col[p + 1] * 32 + t]);
        add8(acc, hadd2x4(v0, v1));
    }
    if (p < cnt) add8(acc, __ldg(&xr[(size_t)col[p] * 32 + t]));

    float ni = rsqrtf((float)deg);
    uint4 o;
    *(__half2*)&o.x = __floats2half2_rn(ni * acc[0], ni * acc[1]);
    *(__half2*)&o.y = __floats2half2_rn(ni * acc[2], ni * acc[3]);
    *(__half2*)&o.z = __floats2half2_rn(ni * acc[4], ni * acc[5]);
    *(__half2*)&o.w = __floats2half2_rn(ni * acc[6], ni * acc[7]);
    ((uint4*)g_ah)[(size_t)node * 32 + t] = o;
}

// ---------------- fp16 mma GEMM: h = relu(agg @ W1^T + b1), fused pool ----------------
// Block 128x128, BK=32 halves, double-buffered cp.async; 8 warps 2(M)x4(N), warp 64x32.
#define ASTR 40                                     // halves per smem row (80B, conflict-free)
#define SM_A 0                                      // [2][128*ASTR] halves
#define SM_B (2 * 128 * ASTR)                       // [2][128*ASTR]
#define SM_C (4 * 128 * ASTR)                       // Ct [128][132] halves
#define CT_STRIDE 132
#define SM_SB (SM_C + 128 * CT_STRIDE)              // sb [128] ints (half-indexed)
#define GEMM_SMEM ((SM_SB + 256) * 2)               // bytes

__device__ __forceinline__ void mma16816(float* c, const uint32_t* a, const uint32_t* b) {
    asm volatile(
        "mma.sync.aligned.m16n8k16.row.col.f32.f16.f16.f32 "
        "{%0,%1,%2,%3}, {%4,%5,%6,%7}, {%8,%9}, {%0,%1,%2,%3};"
        : "+f"(c[0]), "+f"(c[1]), "+f"(c[2]), "+f"(c[3])
        : "r"(a[0]), "r"(a[1]), "r"(a[2]), "r"(a[3]), "r"(b[0]), "r"(b[1]));
}

__global__ void __launch_bounds__(256, 2) k_gemm(const float* __restrict__ b1,
                                                 const void* batch) {
    extern __shared__ __half sh[];
    __half* Ct = sh + SM_C;
    int* sb = (int*)(sh + SM_SB);
    uint32_t sbase = smem_u32(sh);

    int tid = threadIdx.x;
    int wid = tid >> 5, lane = tid & 31;
    int m0 = blockIdx.y * 128, n0 = blockIdx.x * 128;
    int wm = (wid & 1) * 64, wn = (wid >> 1) * 32;
    int g4 = lane >> 2, t4 = lane & 3;

    float c[4][4][4];
#pragma unroll
    for (int a = 0; a < 4; a++)
#pragma unroll
        for (int b = 0; b < 4; b++)
#pragma unroll
            for (int k = 0; k < 4; k++) c[a][b][k] = 0.f;

    int lr = tid >> 2, lq = (tid & 3) * 8;

    auto issue = [&](int buf, int k0) {
#pragma unroll
        for (int it = 0; it < 2; it++) {
            int r = lr + it * 64;
            int m = m0 + r;
            const __half* ga = &g_ah[(size_t)(m < NN ? m : 0) * DD + k0 + lq];
            uint32_t sa = sbase + (SM_A + buf * 128 * ASTR + r * ASTR + lq) * 2;
            CP_ASYNC16(sa, ga, (m < NN) ? 16 : 0);
            const __half* gb = &g_w1h[(n0 + r) * DD + k0 + lq];
            uint32_t sbb = sbase + (SM_B + buf * 128 * ASTR + r * ASTR + lq) * 2;
            CP_ASYNC16(sbb, gb, 16);
        }
        CP_COMMIT();
    };

    issue(0, 0);
    for (int i = 0; i < 8; i++) {
        if (i < 7) { issue((i + 1) & 1, (i + 1) * 32); CP_WAIT(1); }
        else       { CP_WAIT(0); }
        __syncthreads();

        const __half* A = sh + SM_A + (i & 1) * 128 * ASTR;
        const __half* B = sh + SM_B + (i & 1) * 128 * ASTR;
#pragma unroll
        for (int ks = 0; ks < 2; ks++) {
            int kk = ks * 16;
            uint32_t af[4][4], bf[4][2];
#pragma unroll
            for (int mf = 0; mf < 4; mf++) {
                int row = wm + mf * 16;
                af[mf][0] = *(const uint32_t*)&A[(row + g4) * ASTR + kk + 2 * t4];
                af[mf][1] = *(const uint32_t*)&A[(row + 8 + g4) * ASTR + kk + 2 * t4];
                af[mf][2] = *(const uint32_t*)&A[(row + g4) * ASTR + kk + 8 + 2 * t4];
                af[mf][3] = *(const uint32_t*)&A[(row + 8 + g4) * ASTR + kk + 8 + 2 * t4];
            }
#pragma unroll
            for (int nf = 0; nf < 4; nf++) {
                int nr = wn + nf * 8 + g4;
                bf[nf][0] = *(const uint32_t*)&B[nr * ASTR + kk + 2 * t4];
                bf[nf][1] = *(const uint32_t*)&B[nr * ASTR + kk + 8 + 2 * t4];
            }
#pragma unroll
            for (int mf = 0; mf < 4; mf++)
#pragma unroll
                for (int nf = 0; nf < 4; nf++) mma16816(c[mf][nf], af[mf], bf[nf]);
        }
        __syncthreads();
    }

    // epilogue: bias + relu -> Ct (half)
#pragma unroll
    for (int mf = 0; mf < 4; mf++) {
        int mr = wm + mf * 16 + g4;
#pragma unroll
        for (int nf = 0; nf < 4; nf++) {
            int nc = wn + nf * 8 + t4 * 2;
            float bi0 = b1[n0 + nc], bi1 = b1[n0 + nc + 1];
            *(__half2*)&Ct[mr * CT_STRIDE + nc] =
                __floats2half2_rn(fmaxf(c[mf][nf][0] + bi0, 0.f), fmaxf(c[mf][nf][1] + bi1, 0.f));
            *(__half2*)&Ct[(mr + 8) * CT_STRIDE + nc] =
                __floats2half2_rn(fmaxf(c[mf][nf][2] + bi0, 0.f), fmaxf(c[mf][nf][3] + bi1, 0.f));
        }
    }
    if (tid < 128) {
        int m = m0 + tid;
        sb[tid] = (m < NN) ? load_i(batch, g_flags[1], m) : -1;
    }
    __syncthreads();

    // pooling: batch sorted -> run-length max per column, few atomics per block
    int col = tid & 127;
    int r0 = (tid >> 7) * 64;
    int cur = sb[r0];
    float mx = __half2float(Ct[r0 * CT_STRIDE + col]);
    for (int r = r0 + 1; r < r0 + 64; r++) {
        int gg = sb[r];
        float v = __half2float(Ct[r * CT_STRIDE + col]);
        if (gg != cur) {
            if (cur >= 0) atomicMax(&g_pooled[cur * HH + n0 + col], __float_as_uint(mx));
            cur = gg; mx = v;
        } else {
            mx = fmaxf(mx, v);
        }
    }
    if (cur >= 0) atomicMax(&g_pooled[cur * HH + n0 + col], __float_as_uint(mx));
}

// out[g] = pooled[g,:] . W2 + b2
__global__ void k_out(const float* __restrict__ W2, const float* __restrict__ b2,
                      float* __restrict__ out) {
    int warp = (blockIdx.x * blockDim.x + threadIdx.x) >> 5;
    int lane = threadIdx.x & 31;
    if (warp >= GG) return;
    float s = 0.f;
    for (int c = lane; c < HH; c += 32)
        s += __uint_as_float(g_pooled[warp * HH + c]) * W2[c];
#pragma unroll
    for (int off = 16; off; off >>= 1) s += __shfl_down_sync(0xffffffffu, s, off);
    if (lane == 0) out[warp] = s + b2[0];
}

// ---------------- launch ----------------
extern "C" void kernel_launch(void* const* d_in, const int* in_sizes, int n_in,
                              void* d_out, int out_size) {
    const float* x   = (const float*)d_in[0];
    const void*  ei  = d_in[1];
    const void*  bat = d_in[2];
    const float* W1  = (const float*)d_in[3];
    const float* b1  = (const float*)d_in[4];
    const float* W2  = (const float*)d_in[5];
    const float* b2  = (const float*)d_in[6];
    float* out = (float*)d_out;

    static bool attr_done = false;
    if (!attr_done) {
        cudaFuncSetAttribute(k_gemm, cudaFuncAttributeMaxDynamicSharedMemorySize, GEMM_SMEM);
        attr_done = true;
    }

    k_prep<<<256, 256>>>(W1, (const int*)ei, (const int*)bat);
    k_fill<<<(EE / 2 + 255) / 256, 256>>>(ei);
    k_half<<<(NN * 32 + 255) / 256, 256>>>(x);
    k_agg<<<(NN + 7) / 8, 256>>>();
    dim3 gg(HH / 128, (NN + 127) / 128);
    k_gemm<<<gg, 256, GEMM_SMEM>>>(b1, bat);
    k_out<<<(GG * 32 + 127) / 128, 128>>>(W2, b2, out);
}